// round 15
// baseline (speedup 1.0000x reference)
#include <cuda_runtime.h>
#include <cuda_fp16.h>
#include <math_constants.h>
#include <cstdint>
#include <cstring>

// ---------------- problem constants ----------------
#define HH 224
#define WW 224
#define CC 1024
#define BB 256
#define KK (HH * WW)            // 50176
#define EPS_F 0.001f
#define NUMPIX 50176.0f

// ---------------- tiling ----------------
#define KSPLIT 8
#define HSEG (HH / KSPLIT)      // 28 h-rows per CTA
#define KSEG (HSEG * WW)        // 6272
#define KB 32                   // k per iteration (two mma k-steps)
#define WBLK (WW / KB)          // 7 k-blocks per h-row
#define NIT (KSEG / KB)         // 196 iterations
#define MT 128
#define NT 128
#define NTHREADS 512
#define NCTA 128                // 2 (m) x 8 (n) x 8 (k-seg)  == derived, not free!
#define TILE_SZ (128 * 64)      // 8192 B: 128 rows x 32 halfs (64B), XOR-swizzled

// XOR swizzle: chunk c (16B) of row r lives at r*64 + ((c ^ ((r>>1)&3))<<4).
// Conflict-free for ldmatrix (8 rows hit 8 distinct 16B bank-groups).
#define SWOFF(r, c) ((r) * 64 + (((c) ^ (((r) >> 1) & 3)) << 4))

// ---------------- device-global scratch (no allocs allowed) ----------------
__device__ __align__(16) __half g_xhi[(size_t)BB * KK];   // 25.7 MB
__device__ __align__(16) __half g_xlo[(size_t)BB * KK];   // 25.7 MB
__device__ __align__(16) float g_ExT[CC * WW];            // [c][w]
__device__ __align__(16) float g_EyT[HH * CC];            // [h][c] * factor*cw/HW
__device__ __align__(16) float g_part[KSPLIT * BB * CC];  // 8 MB partials

// ---------------- PTX helpers ----------------
__device__ __forceinline__ void cp_async16(void* smem_dst, const void* gsrc) {
    unsigned s = (unsigned)__cvta_generic_to_shared(smem_dst);
    asm volatile("cp.async.cg.shared.global [%0], [%1], 16;\n" ::"r"(s), "l"(gsrc));
}
__device__ __forceinline__ void cp_commit() {
    asm volatile("cp.async.commit_group;\n" ::: "memory");
}
__device__ __forceinline__ void cp_wait1() {
    asm volatile("cp.async.wait_group 1;\n" ::: "memory");
}
__device__ __forceinline__ void ldsm_x4(uint32_t* r, uint32_t addr) {
    asm volatile("ldmatrix.sync.aligned.m8n8.x4.shared.b16 {%0,%1,%2,%3}, [%4];"
                 : "=r"(r[0]), "=r"(r[1]), "=r"(r[2]), "=r"(r[3]) : "r"(addr));
}
__device__ __forceinline__ void mma16816(float* d, const uint32_t* a, const uint32_t* b) {
    asm volatile(
        "mma.sync.aligned.m16n8k16.row.col.f32.f16.f16.f32 "
        "{%0,%1,%2,%3}, {%4,%5,%6,%7}, {%8,%9}, {%0,%1,%2,%3};"
        : "+f"(d[0]), "+f"(d[1]), "+f"(d[2]), "+f"(d[3])
        : "r"(a[0]), "r"(a[1]), "r"(a[2]), "r"(a[3]), "r"(b[0]), "r"(b[1]));
}
__device__ __forceinline__ uint32_t h2_u32(__half2 v) {
    uint32_t u; memcpy(&u, &v, 4); return u;
}

// ---------------- prep: split x into fp16 hi/lo ----------------------------
__global__ void xsplit_kernel(const float* __restrict__ x) {
    int i = blockIdx.x * 256 + threadIdx.x;         // BB*KK total (exact)
    float v = x[i];
    __half hi = __float2half_rn(v);
    g_xhi[i] = hi;
    g_xlo[i] = __float2half_rn(v - __half2float(hi));
}

// ---------------- prep: separable Gaussian tables ---------------------------
__global__ void tables_kernel(const float* __restrict__ positions,
                              const float* __restrict__ sigmas,
                              const float* __restrict__ curve_weights,
                              const float* __restrict__ xs,
                              const float* __restrict__ ys) {
    int c = blockIdx.x;          // 0..1023
    int t = threadIdx.x;         // 0..223
    float p0 = positions[2 * c];
    float p1 = positions[2 * c + 1];
    float s  = sigmas[c];
    float cw = curve_weights[c];
    float s2 = s * s;
    float ts2 = 2.0f * s2 + EPS_F;
    float fcw = cw / ((2.0f * CUDART_PI_F * s2 + EPS_F) * NUMPIX);

    float dx = xs[t] - p1;                          // xs row 0 = x_axis
    g_ExT[c * WW + t] = expf(-(dx * dx) / ts2);
    float dy = ys[t * WW] - p0;                     // ys col 0 = y_axis
    g_EyT[t * CC + c] = expf(-(dy * dy) / ts2) * fcw;
}

// ---------------- main split-fp16 HMMA GEMM ---------------------------------
// out = (xh + xl) * fp16(curve):  2 MMA terms per k-step.
// grid = NCTA = 128: mt = bx&1, nt = (bx>>1)&7, ks = bx>>4 (ks MUST be < 8)
// g_part written via device symbol (NEVER pass __device__ global addr from host
// — the host shadow is silently writable on GB300 via ATS).
__global__ void __launch_bounds__(NTHREADS, 1)
gemm_kernel() {
    __shared__ __align__(16) char sAh[2][TILE_SZ];
    __shared__ __align__(16) char sAl[2][TILE_SZ];
    __shared__ __align__(16) char sB [2][TILE_SZ];   // total 49152 B

    const int tid  = threadIdx.x;
    const int lane = tid & 31;
    const int wid  = tid >> 5;
    const int bx = blockIdx.x;
    const int mt = bx & 1, nt = (bx >> 1) & 7, ks = bx >> 4;
    const int b0 = mt * MT, c0 = nt * NT, h0 = ks * HSEG;
    const size_t kseg0 = (size_t)ks * KSEG;

    const int warp_m = wid >> 2, warp_n = wid & 3;   // 4x4 warp grid
    const int mbase = warp_m * 32, nbase = warp_n * 32;

    const uint32_t uAh = (uint32_t)__cvta_generic_to_shared(&sAh[0][0]);
    const uint32_t uAl = (uint32_t)__cvta_generic_to_shared(&sAl[0][0]);
    const uint32_t uB  = (uint32_t)__cvta_generic_to_shared(&sB [0][0]);

    // ldmatrix lane geometry: row = base + (lane&15), k-chunk = lane>>4
    const int arow = (lane & 15);
    const int achk = (lane >> 4);

    // A-staging coords: tid<256 -> hi limb, else lo. Each thread: 2 x 16B chunks.
    const int tt = tid & 255;
    const int sr = tt >> 1;                    // row 0..127
    const int sc0 = (tt & 1) * 2;              // chunks {0,1} or {2,3}
    const __half* asrc_row =
        (tid < 256 ? g_xhi : g_xlo) + (size_t)(b0 + sr) * KK + kseg0;
    char* adst_tile = (tid < 256 ? &sAh[0][0] : &sAl[0][0]);

    // B-gen coords: thread -> (row gc = tid>>2, chunk gch = tid&3 -> 8 w values)
    const int gc = tid >> 2;
    const int gch = tid & 3;
    const float* eyp = g_EyT + c0 + gc;
    const float* exq = g_ExT + (size_t)(c0 + gc) * WW + gch * 8;
    const uint32_t gb_off = (uint32_t)SWOFF(gc, gch);

    float acc[2][4][4];
#pragma unroll
    for (int i = 0; i < 2; i++)
#pragma unroll
        for (int j = 0; j < 4; j++)
#pragma unroll
            for (int r = 0; r < 4; r++) acc[i][j][r] = 0.0f;

    // ---- prologue: stage iter 0 into stage 0 ----
    {
        cp_async16(adst_tile + SWOFF(sr, sc0),     asrc_row + sc0 * 8);
        cp_async16(adst_tile + SWOFF(sr, sc0 + 1), asrc_row + (sc0 + 1) * 8);
        cp_commit();
        float ey = eyp[(size_t)h0 * CC];
        float4 e0 = *(const float4*)exq;
        float4 e1 = *(const float4*)(exq + 4);
        __half2 p0 = __floats2half2_rn(ey * e0.x, ey * e0.y);
        __half2 p1 = __floats2half2_rn(ey * e0.z, ey * e0.w);
        __half2 p2 = __floats2half2_rn(ey * e1.x, ey * e1.y);
        __half2 p3 = __floats2half2_rn(ey * e1.z, ey * e1.w);
        *(uint4*)(&sB[0][0] + gb_off) =
            make_uint4(h2_u32(p0), h2_u32(p1), h2_u32(p2), h2_u32(p3));
    }

#pragma unroll 1
    for (int kb = 0; kb < NIT; kb++) {
        const int s = kb & 1;

        // ---- prefetch iter kb+1 into the other stage ----
        if (kb + 1 < NIT) {
            const int ns = s ^ 1;
            const size_t koff = (size_t)(kb + 1) * KB;
            cp_async16(adst_tile + ns * TILE_SZ + SWOFF(sr, sc0),
                       asrc_row + koff + sc0 * 8);
            cp_async16(adst_tile + ns * TILE_SZ + SWOFF(sr, sc0 + 1),
                       asrc_row + koff + (sc0 + 1) * 8);
            const int hl = (kb + 1) / WBLK;
            const int wb = (kb + 1) % WBLK;
            float ey = eyp[(size_t)(h0 + hl) * CC];
            const float* eptr = exq + wb * KB;
            float4 e0 = *(const float4*)eptr;
            float4 e1 = *(const float4*)(eptr + 4);
            __half2 p0 = __floats2half2_rn(ey * e0.x, ey * e0.y);
            __half2 p1 = __floats2half2_rn(ey * e0.z, ey * e0.w);
            __half2 p2 = __floats2half2_rn(ey * e1.x, ey * e1.y);
            __half2 p3 = __floats2half2_rn(ey * e1.z, ey * e1.w);
            *(uint4*)(&sB[ns][0] + gb_off) =
                make_uint4(h2_u32(p0), h2_u32(p1), h2_u32(p2), h2_u32(p3));
        }
        cp_commit();            // empty group on last iter keeps wait semantics
        cp_wait1();             // A(kb) complete; next group may fly
        __syncthreads();        // gen(kb) STS + cp.async(kb) visible to all

        // ---- compute on stage s: 2 k-steps x (2 terms x 2 mf x 4 nf) MMAs ----
        const uint32_t so = (uint32_t)(s * TILE_SZ);
#pragma unroll
        for (int kstep = 0; kstep < 2; kstep++) {
            uint32_t aH[2][4], aL[2][4];
#pragma unroll
            for (int mf = 0; mf < 2; mf++) {
                int r = mbase + mf * 16 + arow;
                uint32_t off = so + (uint32_t)SWOFF(r, kstep * 2 + achk);
                ldsm_x4(aH[mf], uAh + off);
                ldsm_x4(aL[mf], uAl + off);
            }
            uint32_t q[4];
            uint32_t bF[4][2];
            {
                int r = nbase + arow;
                ldsm_x4(q, uB + so + (uint32_t)SWOFF(r, kstep * 2 + achk));
                bF[0][0] = q[0]; bF[0][1] = q[2];
                bF[1][0] = q[1]; bF[1][1] = q[3];
                r = nbase + 16 + arow;
                ldsm_x4(q, uB + so + (uint32_t)SWOFF(r, kstep * 2 + achk));
                bF[2][0] = q[0]; bF[2][1] = q[2];
                bF[3][0] = q[1]; bF[3][1] = q[3];
            }
#pragma unroll
            for (int mf = 0; mf < 2; mf++)
#pragma unroll
                for (int nf = 0; nf < 4; nf++) {
                    mma16816(acc[mf][nf], aH[mf], bF[nf]);
                    mma16816(acc[mf][nf], aL[mf], bF[nf]);
                }
        }
        __syncthreads();        // done reading stage s before it is re-staged
    }

    // ---- epilogue: write partial tile to g_part (deterministic k-split) ----
    float* pbase = g_part + (size_t)ks * BB * CC;
#pragma unroll
    for (int mf = 0; mf < 2; mf++)
#pragma unroll
        for (int nf = 0; nf < 4; nf++)
#pragma unroll
            for (int pr = 0; pr < 2; pr++) {
                int row = b0 + mbase + mf * 16 + (lane >> 2) + pr * 8;
                int col = c0 + nbase + nf * 8 + (lane & 3) * 2;
                float2 v = make_float2(acc[mf][nf][pr * 2], acc[mf][nf][pr * 2 + 1]);
                *(float2*)&pbase[(size_t)row * CC + col] = v;
            }
}

// ---------------- reduce the 8 k-split partials -----------------------------
__global__ void reduce_kernel(float* __restrict__ out) {
    int i = blockIdx.x * 256 + threadIdx.x;    // 0..262143
    float s = 0.0f;
#pragma unroll
    for (int k = 0; k < KSPLIT; k++) s += g_part[(size_t)k * BB * CC + i];
    out[i] = s;
}

// ---------------- launch ----------------------------------------------------
extern "C" void kernel_launch(void* const* d_in, const int* in_sizes, int n_in,
                              void* d_out, int out_size) {
    const float* x   = (const float*)d_in[0];
    const float* pos = (const float*)d_in[1];
    const float* sig = (const float*)d_in[2];
    const float* cwt = (const float*)d_in[3];
    const float* xs  = (const float*)d_in[4];
    const float* ys  = (const float*)d_in[5];
    float* out = (float*)d_out;

    xsplit_kernel<<<(BB * KK) / 256, 256>>>(x);
    tables_kernel<<<CC, HH>>>(pos, sig, cwt, xs, ys);
    gemm_kernel<<<NCTA, NTHREADS>>>();     // NCTA = 2*8*KSPLIT = 128, derived
    reduce_kernel<<<(BB * CC) / 256, 256>>>(out);
}